// round 9
// baseline (speedup 1.0000x reference)
#include <cuda_runtime.h>
#include <cuda_bf16.h>
#include <cstdint>

#define WARPS_PER_CTA 14
#define THREADS (WARPS_PER_CTA * 32)
#define N_GROUPS 4096              // 32768 rows / 8
#define ACTIVE_WARPS 2048          // each does exactly 2 groups

// Dynamic smem layout (float indices):
//  [0,12288)      W_code  96x128
//  [12288,20480)  W_h1   128x64
//  [20480,22528)  W_h2    64x32
//  [22528,23040)  W_h3    32x16
//  [23040,23088)  W_h4    16x3
//  [23088,23216)  b_code
//  [23216,23280)  b_h1
//  [23280,23312)  b_h2
//  [23312,23328)  b_h3
//  [23328,23331)  b_h4
//  [23344, +14*2304) per-warp buffers (16B aligned)
#define OFF_WC 0
#define OFF_W1 12288
#define OFF_W2 20480
#define OFF_W3 22528
#define OFF_W4 23040
#define OFF_BC 23088
#define OFF_B1 23216
#define OFF_B2 23280
#define OFF_B3 23312
#define OFF_B4 23328
#define OFF_BUF 23344
#define BUF_FLOATS 2304
#define SMEM_BYTES ((OFF_BUF + WARPS_PER_CTA * BUF_FLOATS) * 4)   // 222400

typedef unsigned long long u64;

__device__ __forceinline__ u64 fma2(u64 a, u64 b, u64 c) {
    u64 d;
    asm("fma.rn.f32x2 %0, %1, %2, %3;" : "=l"(d) : "l"(a), "l"(b), "l"(c));
    return d;
}
__device__ __forceinline__ u64 pack2(float x, float y) {
    u64 d;
    asm("mov.b64 %0, {%1, %2};" : "=l"(d) : "r"(__float_as_uint(x)), "r"(__float_as_uint(y)));
    return d;
}
__device__ __forceinline__ u64 splat2(float x) {
    u64 d;
    asm("mov.b64 %0, {%1, %1};" : "=l"(d) : "r"(__float_as_uint(x)));
    return d;
}
__device__ __forceinline__ void unpack2(u64 a, float& x, float& y) {
    unsigned lo, hi;
    asm("mov.b64 {%0, %1}, %2;" : "=r"(lo), "=r"(hi) : "l"(a));
    x = __uint_as_float(lo); y = __uint_as_float(hi);
}
__device__ __forceinline__ u64 max2(u64 a, u64 b) {
    float a0, a1, b0, b1;
    unpack2(a, a0, a1); unpack2(b, b0, b1);
    return pack2(fmaxf(a0, b0), fmaxf(a1, b1));
}
__device__ __forceinline__ u64 relu2(u64 x) {
    float x0, x1;
    unpack2(x, x0, x1);
    return pack2(fmaxf(x0, 0.f), fmaxf(x1, 0.f));
}
__device__ __forceinline__ u64 leaky2(u64 x) {
    float x0, x1;
    unpack2(x, x0, x1);
    return pack2(fmaxf(x0, 0.2f * x0), fmaxf(x1, 0.2f * x1));
}

__global__ __launch_bounds__(THREADS)
void flatnet_r8s_kernel(
    const float* __restrict__ pgi,
    const float* __restrict__ W_lift, const float* __restrict__ b_lift,
    const float* __restrict__ W_code, const float* __restrict__ b_code,
    const float* __restrict__ W_h1,   const float* __restrict__ b_h1,
    const float* __restrict__ W_h2,   const float* __restrict__ b_h2,
    const float* __restrict__ W_h3,   const float* __restrict__ b_h3,
    const float* __restrict__ W_h4,   const float* __restrict__ b_h4,
    float* __restrict__ out)
{
    extern __shared__ __align__(16) float dsm[];

    const int tid  = threadIdx.x;
    const int warp = tid >> 5;
    const int lane = tid & 31;

    // ---- Cooperative load of ALL weights into shared memory (once per CTA) ----
    for (int i = tid; i < 12288; i += THREADS) dsm[OFF_WC + i] = W_code[i];
    for (int i = tid; i < 8192;  i += THREADS) dsm[OFF_W1 + i] = W_h1[i];
    for (int i = tid; i < 2048;  i += THREADS) dsm[OFF_W2 + i] = W_h2[i];
    for (int i = tid; i < 512;   i += THREADS) dsm[OFF_W3 + i] = W_h3[i];
    if (tid < 48)  dsm[OFF_W4 + tid] = W_h4[tid];
    if (tid < 128) dsm[OFF_BC + tid] = b_code[tid];
    if (tid < 64)  dsm[OFF_B1 + tid] = b_h1[tid];
    if (tid < 32)  dsm[OFF_B2 + tid] = b_h2[tid];
    if (tid < 16)  dsm[OFF_B3 + tid] = b_h3[tid];
    if (tid < 3)   dsm[OFF_B4 + tid] = b_h4[tid];
    __syncthreads();

    const float* sWc = dsm + OFF_WC;
    const float* sW1 = dsm + OFF_W1;
    const float* sW2 = dsm + OFF_W2;
    const float* sW3 = dsm + OFF_W3;
    const float* sW4 = dsm + OFF_W4;

    const int wg = blockIdx.x * WARPS_PER_CTA + warp;   // 0 .. 2071
    if (wg >= ACTIVE_WARPS) return;

    float* buf = dsm + OFF_BUF + warp * BUF_FLOATS;
    const int ld3 = lane / 3, lm3 = lane - ld3 * 3;

    // lift weights stay in registers (tiny, L1-resident)
    const u64 ww0 = splat2(__ldg(W_lift + lane));
    const u64 ww1 = splat2(__ldg(W_lift + 32 + lane));
    const u64 ww2 = splat2(__ldg(W_lift + 64 + lane));
    const u64 bbl = splat2(__ldg(b_lift + lane));

    #pragma unroll 1
    for (int it = 0; it < 2; it++) {
        const int wrow = (wg * 2 + it) * 8;             // base row = b*1024+g

        // ---- Stage 8 rows' 8x8 point blocks (evict-first stream) ----
        {
            const int b = wrow >> 10, g = wrow & 1023;
            const int gi = g >> 5, gj = g & 31;
            const float* base = pgi + ((size_t)b * 65536 + (size_t)(gi * 8) * 256 + (size_t)(gj * 8)) * 3;
            if (lane < 24) {
                #pragma unroll
                for (int q = 0; q < 8; q++) {
                    const int P = q >> 1, s = q & 1;
                    const float* bq = base + q * 24;
                    #pragma unroll
                    for (int gr = 0; gr < 8; gr++) {
                        const float val = __ldcs(bq + (size_t)gr * 768 + lane);
                        const int p = gr * 8 + ld3;
                        int off;
                        if (lm3 == 2) off = 1024 + P * 128 + p * 2 + s;       // z
                        else          off = P * 256 + p * 4 + lm3 * 2 + s;    // x / y
                        buf[off] = val;
                    }
                }
            }
        }
        __syncwarp();

        // ---- Lift (lane = channel), row-pairs packed; ring-major v stores ----
        #pragma unroll
        for (int P = 0; P < 4; P++) {
            const float* XY = buf + P * 256;
            const float* Z  = buf + 1024 + P * 128;
            u64 mi = pack2(-3.0e38f, -3.0e38f);
            u64 mt = mi, mo = mi;
            #pragma unroll
            for (int p = 0; p < 64; p += 2) {
                const ulonglong2 xyA = *(const ulonglong2*)(XY + p * 4);
                const ulonglong2 xyB = *(const ulonglong2*)(XY + p * 4 + 4);
                const ulonglong2 zz  = *(const ulonglong2*)(Z + p * 2);
                const u64 hA = fma2(xyA.x, ww0, fma2(xyA.y, ww1, fma2(zz.x, ww2, bbl)));
                const u64 hB = fma2(xyB.x, ww0, fma2(xyB.y, ww1, fma2(zz.y, ww2, bbl)));
                {
                    const int r = p >> 3, c = p & 7;
                    const int d = min(min(r, c), min(7 - r, 7 - c));
                    if (d == 3)      mi = max2(mi, hA);
                    else if (d == 2) mt = max2(mt, hA);
                    else             mo = max2(mo, hA);
                }
                {
                    const int r = (p + 1) >> 3, c = (p + 1) & 7;
                    const int d = min(min(r, c), min(7 - r, 7 - c));
                    if (d == 3)      mi = max2(mi, hB);
                    else if (d == 2) mt = max2(mt, hB);
                    else             mo = max2(mo, hB);
                }
            }
            // v' index: i' = lane*3 + ring (ring 0=inner,1=inter,2=outer)
            float* vdst = buf + ((P < 2) ? 1536 : 1920);
            const int qb = (P & 1) * 2;
            *(u64*)(vdst + (lane * 3 + 0) * 4 + qb) = leaky2(mi);
            *(u64*)(vdst + (lane * 3 + 1) * 4 + qb) = leaky2(mt);
            *(u64*)(vdst + (lane * 3 + 2) * 4 + qb) = leaky2(mo);
        }
        __syncwarp();

        // ---- v_code[128] = leaky(v @ W_code + b); lane owns j=lane+32o.
        //      v ring-major: i'=ch*3+ring <-> W_code row = ring*32+ch (smem). ----
        {
            u64 aA[4][2], aB[4][2];
            #pragma unroll
            for (int o = 0; o < 4; o++) {
                const u64 bsp = splat2(dsm[OFF_BC + 32 * o + lane]);
                aA[o][0] = bsp; aA[o][1] = bsp;
                aB[o][0] = bsp; aB[o][1] = bsp;
            }
            #pragma unroll 2
            for (int ch = 0; ch < 32; ch++) {
                #pragma unroll
                for (int ring = 0; ring < 3; ring++) {
                    const int ii = ch * 3 + ring;
                    const ulonglong2 vA = *(const ulonglong2*)(buf + 1536 + ii * 4);
                    const ulonglong2 vB = *(const ulonglong2*)(buf + 1920 + ii * 4);
                    const float* wr = sWc + (ring * 32 + ch) * 128 + lane;
                    #pragma unroll
                    for (int o = 0; o < 4; o++) {
                        const u64 ww = splat2(wr[32 * o]);
                        aA[o][0] = fma2(vA.x, ww, aA[o][0]);
                        aA[o][1] = fma2(vA.y, ww, aA[o][1]);
                        aB[o][0] = fma2(vB.x, ww, aB[o][0]);
                        aB[o][1] = fma2(vB.y, ww, aB[o][1]);
                    }
                }
            }
            __syncwarp();
            #pragma unroll
            for (int o = 0; o < 4; o++) {
                const int ch = 32 * o + lane;
                ulonglong2 rA = { leaky2(aA[o][0]), leaky2(aA[o][1]) };
                ulonglong2 rB = { leaky2(aB[o][0]), leaky2(aB[o][1]) };
                *(ulonglong2*)(buf + ch * 4)       = rA;   // act rows 0-3
                *(ulonglong2*)(buf + 512 + ch * 4) = rB;   // act rows 4-7
            }
        }
        __syncwarp();

        // ---- h1[64] = relu(v_code @ W_h1 + b) ----
        {
            u64 cA[2][2], cB[2][2];
            #pragma unroll
            for (int o = 0; o < 2; o++) {
                const u64 bsp = splat2(dsm[OFF_B1 + 32 * o + lane]);
                cA[o][0] = bsp; cA[o][1] = bsp;
                cB[o][0] = bsp; cB[o][1] = bsp;
            }
            #pragma unroll 4
            for (int i = 0; i < 128; i++) {
                const ulonglong2 vA = *(const ulonglong2*)(buf + i * 4);
                const ulonglong2 vB = *(const ulonglong2*)(buf + 512 + i * 4);
                const float* wr = sW1 + i * 64 + lane;
                #pragma unroll
                for (int o = 0; o < 2; o++) {
                    const u64 ww = splat2(wr[32 * o]);
                    cA[o][0] = fma2(vA.x, ww, cA[o][0]);
                    cA[o][1] = fma2(vA.y, ww, cA[o][1]);
                    cB[o][0] = fma2(vB.x, ww, cB[o][0]);
                    cB[o][1] = fma2(vB.y, ww, cB[o][1]);
                }
            }
            __syncwarp();
            #pragma unroll
            for (int o = 0; o < 2; o++) {
                const int ch = 32 * o + lane;
                ulonglong2 rA = { relu2(cA[o][0]), relu2(cA[o][1]) };
                ulonglong2 rB = { relu2(cB[o][0]), relu2(cB[o][1]) };
                *(ulonglong2*)(buf + 1536 + ch * 4) = rA;  // h1A
                *(ulonglong2*)(buf + 1792 + ch * 4) = rB;  // h1B
            }
        }
        __syncwarp();

        // ---- h2[32] = relu(h1 @ W_h2 + b) ----
        {
            u64 dA[2], dB[2];
            {
                const u64 bsp = splat2(dsm[OFF_B2 + lane]);
                dA[0] = bsp; dA[1] = bsp;
                dB[0] = bsp; dB[1] = bsp;
            }
            #pragma unroll 8
            for (int i = 0; i < 64; i++) {
                const ulonglong2 vA = *(const ulonglong2*)(buf + 1536 + i * 4);
                const ulonglong2 vB = *(const ulonglong2*)(buf + 1792 + i * 4);
                const u64 ww = splat2(sW2[i * 32 + lane]);
                dA[0] = fma2(vA.x, ww, dA[0]);
                dA[1] = fma2(vA.y, ww, dA[1]);
                dB[0] = fma2(vB.x, ww, dB[0]);
                dB[1] = fma2(vB.y, ww, dB[1]);
            }
            __syncwarp();
            ulonglong2 rA = { relu2(dA[0]), relu2(dA[1]) };
            ulonglong2 rB = { relu2(dB[0]), relu2(dB[1]) };
            *(ulonglong2*)(buf + lane * 4)       = rA;     // h2A
            *(ulonglong2*)(buf + 128 + lane * 4) = rB;     // h2B
        }
        __syncwarp();

        // ---- h3[16] = relu(h2 @ W_h3 + b); half-warp per 4-row group ----
        {
            const int j  = lane & 15;
            const int hh = lane >> 4;
            u64 e0, e1;
            {
                const u64 bsp = splat2(dsm[OFF_B3 + j]);
                e0 = bsp; e1 = bsp;
            }
            const float* h2p = buf + hh * 128;
            #pragma unroll 8
            for (int i = 0; i < 32; i++) {
                const ulonglong2 v = *(const ulonglong2*)(h2p + i * 4);
                const u64 ww = splat2(sW3[i * 16 + j]);
                e0 = fma2(v.x, ww, e0);
                e1 = fma2(v.y, ww, e1);
            }
            ulonglong2 r = { relu2(e0), relu2(e1) };
            *(ulonglong2*)(buf + (hh ? 1600 : 1536) + j * 4) = r;  // h3A / h3B
        }
        __syncwarp();

        // ---- out[3] per row; lanes 0..23 -> 24 contiguous floats ----
        if (lane < 24) {
            const float* h3p = buf + ((ld3 < 4) ? (1536 + ld3) : (1600 + (ld3 - 4)));
            float o = dsm[OFF_B4 + lm3];
            #pragma unroll
            for (int i = 0; i < 16; i++)
                o = fmaf(h3p[i * 4], sW4[i * 3 + lm3], o);
            out[(size_t)wrow * 3 + lane] = o;
        }
        __syncwarp();
    }
}

extern "C" void kernel_launch(void* const* d_in, const int* in_sizes, int n_in,
                              void* d_out, int out_size)
{
    const float* pgi    = (const float*)d_in[0];
    const float* W_lift = (const float*)d_in[1];
    const float* b_lift = (const float*)d_in[2];
    const float* W_code = (const float*)d_in[3];
    const float* b_code = (const float*)d_in[4];
    const float* W_h1   = (const float*)d_in[5];
    const float* b_h1   = (const float*)d_in[6];
    const float* W_h2   = (const float*)d_in[7];
    const float* b_h2   = (const float*)d_in[8];
    const float* W_h3   = (const float*)d_in[9];
    const float* b_h3   = (const float*)d_in[10];
    const float* W_h4   = (const float*)d_in[11];
    const float* b_h4   = (const float*)d_in[12];
    float* out = (float*)d_out;

    cudaFuncSetAttribute(flatnet_r8s_kernel,
                         cudaFuncAttributeMaxDynamicSharedMemorySize, SMEM_BYTES);

    // 148 CTAs (1/SM) x 14 warps; warps 0..2047 each process exactly 2
    // consecutive 8-row groups -> 4096 groups = 32768 rows. No tail.
    flatnet_r8s_kernel<<<148, THREADS, SMEM_BYTES>>>(
        pgi, W_lift, b_lift, W_code, b_code,
        W_h1, b_h1, W_h2, b_h2, W_h3, b_h3, W_h4, b_h4, out);
}

// round 11
// speedup vs baseline: 1.5444x; 1.5444x over previous
#include <cuda_runtime.h>
#include <cuda_bf16.h>
#include <cstdint>

#define THREADS 256
#define NWARP 8
// smem byte offsets:
//  fb floats: bc[0..128) b1[128..192) b2[192..224) b3[224..240) b4[240..243) W4[244..292)
#define OFF_B1 1536      // 96 frags  * 512B (W_code 96x128: KT=6, NT=16)
#define OFF_B2 50688     // 64 frags  (W_h1 128x64: KT=8, NT=8)
#define OFF_B3 83456     // 16 frags  (W_h2 64x32: KT=4, NT=4)
#define OFF_B4 91648     // 4 frags   (W_h3 32x16: KT=2, NT=2)
#define OFF_WARP 93696
#define WARP_BYTES 14592 // pts 1536 floats + v 96x22 floats
#define SMEM_BYTES 210432

typedef unsigned long long u64;

// ---- packed fp32 helpers (lift) ----
__device__ __forceinline__ u64 fma2(u64 a, u64 b, u64 c) {
    u64 d; asm("fma.rn.f32x2 %0, %1, %2, %3;" : "=l"(d) : "l"(a), "l"(b), "l"(c)); return d;
}
__device__ __forceinline__ u64 pack2(float x, float y) {
    u64 d; asm("mov.b64 %0, {%1, %2};" : "=l"(d) : "r"(__float_as_uint(x)), "r"(__float_as_uint(y))); return d;
}
__device__ __forceinline__ u64 splat2(float x) {
    u64 d; asm("mov.b64 %0, {%1, %1};" : "=l"(d) : "r"(__float_as_uint(x))); return d;
}
__device__ __forceinline__ void unpack2(u64 a, float& x, float& y) {
    unsigned lo, hi; asm("mov.b64 {%0, %1}, %2;" : "=r"(lo), "=r"(hi) : "l"(a));
    x = __uint_as_float(lo); y = __uint_as_float(hi);
}
__device__ __forceinline__ u64 max2(u64 a, u64 b) {
    float a0, a1, b0, b1; unpack2(a, a0, a1); unpack2(b, b0, b1);
    return pack2(fmaxf(a0, b0), fmaxf(a1, b1));
}
__device__ __forceinline__ u64 leaky2(u64 x) {
    float x0, x1; unpack2(x, x0, x1);
    return pack2(fmaxf(x0, 0.2f * x0), fmaxf(x1, 0.2f * x1));
}
__device__ __forceinline__ float lrelu(float x) { return fmaxf(x, 0.2f * x); }

// split a fp32 pair into bf16 hi and lo (residual) packed u32s; low half = first elem
__device__ __forceinline__ void split_pack(float a, float b, uint32_t& hi, uint32_t& lo) {
    __nv_bfloat16 ha = __float2bfloat16(a), hb = __float2bfloat16(b);
    __nv_bfloat16 la = __float2bfloat16(a - __bfloat162float(ha));
    __nv_bfloat16 lb = __float2bfloat16(b - __bfloat162float(hb));
    hi = (uint32_t)__bfloat16_as_ushort(ha) | ((uint32_t)__bfloat16_as_ushort(hb) << 16);
    lo = (uint32_t)__bfloat16_as_ushort(la) | ((uint32_t)__bfloat16_as_ushort(lb) << 16);
}

// classic HMMA, sm_80+ baseline (no 'a' target feature needed)
__device__ __forceinline__ void mma_bf16(float d[4], const uint32_t a[4], uint32_t b0, uint32_t b1) {
    asm volatile("mma.sync.aligned.m16n8k16.row.col.f32.bf16.bf16.f32 "
        "{%0,%1,%2,%3}, {%4,%5,%6,%7}, {%8,%9}, {%0,%1,%2,%3};"
        : "+f"(d[0]), "+f"(d[1]), "+f"(d[2]), "+f"(d[3])
        : "r"(a[0]), "r"(a[1]), "r"(a[2]), "r"(a[3]), "r"(b0), "r"(b1));
}

// Weights [K][N] row-major -> fragment-major smem: per (frag,lane) 16B {bh0,bh1,bl0,bl1}
__device__ void conv_B(char* dsm, int off, const float* W, int N, int KT, int NT, int tid) {
    const int tot = KT * NT * 32;
    for (int idx = tid; idx < tot; idx += THREADS) {
        const int l = idx & 31, frag = idx >> 5;
        const int nt = frag % NT, kt = frag / NT;
        const int k0 = kt * 16 + 2 * (l & 3), n = nt * 8 + (l >> 2);
        const float w00 = __ldg(W + k0 * N + n),       w01 = __ldg(W + (k0 + 1) * N + n);
        const float w10 = __ldg(W + (k0 + 8) * N + n), w11 = __ldg(W + (k0 + 9) * N + n);
        uint32_t h0, l0, h1, l1;
        split_pack(w00, w01, h0, l0);
        split_pack(w10, w11, h1, l1);
        *(uint4*)(dsm + off + (size_t)idx * 16) = make_uint4(h0, h1, l0, l1);
    }
}

template<int KT, int NT>
__device__ __forceinline__ void do_layer(const char* B, const float* bias,
        const uint32_t ah[][4], const uint32_t al[][4], float d[][4], int lane, int a2) {
    #pragma unroll
    for (int nt = 0; nt < NT; nt++) {
        const float b0 = bias[nt * 8 + a2], b1 = bias[nt * 8 + a2 + 1];
        d[nt][0] = b0; d[nt][1] = b1; d[nt][2] = b0; d[nt][3] = b1;
        #pragma unroll
        for (int kt = 0; kt < KT; kt++) {
            const uint4 q = *(const uint4*)(B + (size_t)((kt * NT + nt) * 32 + lane) * 16);
            mma_bf16(d[nt], ah[kt], q.x, q.y);   // Ah*Bh
            mma_bf16(d[nt], ah[kt], q.z, q.w);   // Ah*Bl
            mma_bf16(d[nt], al[kt], q.x, q.y);   // Al*Bh
        }
    }
}

// D frags (bias pre-added) -> activation -> next layer's A frags (NT/2 k-tiles)
template<int NT, bool LEAKY>
__device__ __forceinline__ void act_to_A(const float d[][4], uint32_t ah[][4], uint32_t al[][4]) {
    #pragma unroll
    for (int p = 0; p < NT / 2; p++) {
        #pragma unroll
        for (int h = 0; h < 2; h++) {
            const float* dd = d[2 * p + h];
            float x0, x1, x2, x3;
            if (LEAKY) { x0 = lrelu(dd[0]); x1 = lrelu(dd[1]); x2 = lrelu(dd[2]); x3 = lrelu(dd[3]); }
            else { x0 = fmaxf(dd[0], 0.f); x1 = fmaxf(dd[1], 0.f); x2 = fmaxf(dd[2], 0.f); x3 = fmaxf(dd[3], 0.f); }
            split_pack(x0, x1, ah[p][2 * h],     al[p][2 * h]);
            split_pack(x2, x3, ah[p][2 * h + 1], al[p][2 * h + 1]);
        }
    }
}

__global__ __launch_bounds__(THREADS)
void flatnet_mma_kernel(
    const float* __restrict__ pgi,
    const float* __restrict__ W_lift, const float* __restrict__ b_lift,
    const float* __restrict__ W_code, const float* __restrict__ b_code,
    const float* __restrict__ W_h1,   const float* __restrict__ b_h1,
    const float* __restrict__ W_h2,   const float* __restrict__ b_h2,
    const float* __restrict__ W_h3,   const float* __restrict__ b_h3,
    const float* __restrict__ W_h4,   const float* __restrict__ b_h4,
    float* __restrict__ out)
{
    extern __shared__ __align__(16) char dsm[];
    float* fb = (float*)dsm;
    const int tid = threadIdx.x, warp = tid >> 5, lane = tid & 31;

    // ---- prologue: biases + fragment-major hi/lo weight tiles ----
    if (tid < 128) fb[tid] = b_code[tid];
    if (tid < 64)  fb[128 + tid] = b_h1[tid];
    if (tid < 32)  fb[192 + tid] = b_h2[tid];
    if (tid < 16)  fb[224 + tid] = b_h3[tid];
    if (tid < 3)   fb[240 + tid] = b_h4[tid];
    if (tid < 48)  fb[244 + tid] = W_h4[tid];
    conv_B(dsm, OFF_B1, W_code, 128, 6, 16, tid);
    conv_B(dsm, OFF_B2, W_h1,    64, 8,  8, tid);
    conv_B(dsm, OFF_B3, W_h2,    32, 4,  4, tid);
    conv_B(dsm, OFF_B4, W_h3,    16, 2,  2, tid);
    __syncthreads();

    // lift constants (lane = channel)
    const u64 ww0 = splat2(__ldg(W_lift + lane));
    const u64 ww1 = splat2(__ldg(W_lift + 32 + lane));
    const u64 ww2 = splat2(__ldg(W_lift + 64 + lane));
    const u64 bbl = splat2(__ldg(b_lift + lane));
    const int ld3 = lane / 3, lm3 = lane - ld3 * 3;
    const int a2 = 2 * (lane & 3), rr = lane >> 2;

    float* pts = (float*)(dsm + OFF_WARP + warp * WARP_BYTES);
    float* vv  = pts + 1536;   // v[k][22] fp32, k = ring*32+ch (standard order)

    for (int t = blockIdx.x * NWARP + warp; t < 2048; t += 148 * NWARP) {
        // ================= LIFT: 16 rows = 2 groups of 8 =================
        #pragma unroll 1
        for (int it = 0; it < 2; it++) {
            const int grow = t * 16 + it * 8;
            const int b = grow >> 10, g = grow & 1023;
            const int gi = g >> 5, gj = g & 31;
            const float* base = pgi + ((size_t)b * 65536 + (size_t)(gi * 8) * 256 + (size_t)(gj * 8)) * 3;
            if (lane < 24) {
                #pragma unroll
                for (int q = 0; q < 8; q++) {
                    const int P = q >> 1, s = q & 1;
                    const float* bq = base + q * 24;
                    #pragma unroll
                    for (int gr = 0; gr < 8; gr++) {
                        const float val = __ldcs(bq + (size_t)gr * 768 + lane);
                        const int p = gr * 8 + ld3;
                        int off;
                        if (lm3 == 2) off = 1024 + P * 128 + p * 2 + s;
                        else          off = P * 256 + p * 4 + lm3 * 2 + s;
                        pts[off] = val;
                    }
                }
            }
            __syncwarp();
            #pragma unroll
            for (int P = 0; P < 4; P++) {
                const float* XY = pts + P * 256;
                const float* Z  = pts + 1024 + P * 128;
                u64 mi = pack2(-3.0e38f, -3.0e38f), mt = mi, mo = mi;
                #pragma unroll
                for (int p = 0; p < 64; p += 2) {
                    const ulonglong2 xyA = *(const ulonglong2*)(XY + p * 4);
                    const ulonglong2 xyB = *(const ulonglong2*)(XY + p * 4 + 4);
                    const ulonglong2 zz  = *(const ulonglong2*)(Z + p * 2);
                    const u64 hA = fma2(xyA.x, ww0, fma2(xyA.y, ww1, fma2(zz.x, ww2, bbl)));
                    const u64 hB = fma2(xyB.x, ww0, fma2(xyB.y, ww1, fma2(zz.y, ww2, bbl)));
                    { const int r = p >> 3, c = p & 7, d = min(min(r, c), min(7 - r, 7 - c));
                      if (d == 3) mi = max2(mi, hA); else if (d == 2) mt = max2(mt, hA); else mo = max2(mo, hA); }
                    { const int r = (p + 1) >> 3, c = (p + 1) & 7, d = min(min(r, c), min(7 - r, 7 - c));
                      if (d == 3) mi = max2(mi, hB); else if (d == 2) mt = max2(mt, hB); else mo = max2(mo, hB); }
                }
                const int rb = it * 8 + P * 2;   // tile rows rb, rb+1 (even => 8B aligned)
                *(u64*)(vv + (lane)      * 22 + rb) = leaky2(mi);   // inner: k = ch
                *(u64*)(vv + (32 + lane) * 22 + rb) = leaky2(mt);   // inter
                *(u64*)(vv + (64 + lane) * 22 + rb) = leaky2(mo);   // outer
            }
            __syncwarp();
        }
        __syncwarp();

        // ================= A1 fragments from v =================
        uint32_t ah[8][4], al[8][4];
        #pragma unroll
        for (int kt = 0; kt < 6; kt++) {
            const float* vk = vv + (kt * 16 + a2) * 22;
            split_pack(vk[rr],           vk[22 + rr],      ah[kt][0], al[kt][0]); // (r,   k0,k0+1)
            split_pack(vk[8 + rr],       vk[30 + rr],      ah[kt][1], al[kt][1]); // (r+8, k0,k0+1)
            split_pack(vk[176 + rr],     vk[198 + rr],     ah[kt][2], al[kt][2]); // (r,   k0+8,+9)
            split_pack(vk[184 + rr],     vk[206 + rr],     ah[kt][3], al[kt][3]); // (r+8, k0+8,+9)
        }

        // ================= MLP chain, all in registers =================
        float d1[16][4];
        do_layer<6, 16>(dsm + OFF_B1, fb,       ah, al, d1, lane, a2);
        act_to_A<16, true >(d1, ah, al);
        float d2[8][4];
        do_layer<8, 8 >(dsm + OFF_B2, fb + 128, ah, al, d2, lane, a2);
        act_to_A<8,  false>(d2, ah, al);
        float d3[4][4];
        do_layer<4, 4 >(dsm + OFF_B3, fb + 192, ah, al, d3, lane, a2);
        act_to_A<4,  false>(d3, ah, al);
        float d4[2][4];
        do_layer<2, 2 >(dsm + OFF_B4, fb + 224, ah, al, d4, lane, a2);

        // ================= tail: h3 -> out (16->3), quad reduce =================
        {
            float h30[4], h31[4];   // rows rr and rr+8; cols a2,a2+1,a2+8,a2+9
            h30[0] = fmaxf(d4[0][0], 0.f); h30[1] = fmaxf(d4[0][1], 0.f);
            h30[2] = fmaxf(d4[1][0], 0.f); h30[3] = fmaxf(d4[1][1], 0.f);
            h31[0] = fmaxf(d4[0][2], 0.f); h31[1] = fmaxf(d4[0][3], 0.f);
            h31[2] = fmaxf(d4[1][2], 0.f); h31[3] = fmaxf(d4[1][3], 0.f);
            float s0[3], s1[3];
            #pragma unroll
            for (int c = 0; c < 3; c++) {
                const float w0 = fb[244 + a2 * 3 + c],        w1 = fb[244 + (a2 + 1) * 3 + c];
                const float w2 = fb[244 + (a2 + 8) * 3 + c],  w3 = fb[244 + (a2 + 9) * 3 + c];
                float t0 = fmaf(h30[0], w0, fmaf(h30[1], w1, fmaf(h30[2], w2, h30[3] * w3)));
                float t1 = fmaf(h31[0], w0, fmaf(h31[1], w1, fmaf(h31[2], w2, h31[3] * w3)));
                t0 += __shfl_xor_sync(0xffffffffu, t0, 1);
                t0 += __shfl_xor_sync(0xffffffffu, t0, 2);
                t1 += __shfl_xor_sync(0xffffffffu, t1, 1);
                t1 += __shfl_xor_sync(0xffffffffu, t1, 2);
                s0[c] = t0 + fb[240 + c];
                s1[c] = t1 + fb[240 + c];
            }
            const int c = lane & 3;
            if (c < 3) {
                const float o0 = (c == 0) ? s0[0] : ((c == 1) ? s0[1] : s0[2]);
                const float o1 = (c == 0) ? s1[0] : ((c == 1) ? s1[1] : s1[2]);
                out[((size_t)t * 16 + rr) * 3 + c]     = o0;
                out[((size_t)t * 16 + rr + 8) * 3 + c] = o1;
            }
        }
    }
}

extern "C" void kernel_launch(void* const* d_in, const int* in_sizes, int n_in,
                              void* d_out, int out_size)
{
    const float* pgi    = (const float*)d_in[0];
    const float* W_lift = (const float*)d_in[1];
    const float* b_lift = (const float*)d_in[2];
    const float* W_code = (const float*)d_in[3];
    const float* b_code = (const float*)d_in[4];
    const float* W_h1   = (const float*)d_in[5];
    const float* b_h1   = (const float*)d_in[6];
    const float* W_h2   = (const float*)d_in[7];
    const float* b_h2   = (const float*)d_in[8];
    const float* W_h3   = (const float*)d_in[9];
    const float* b_h3   = (const float*)d_in[10];
    const float* W_h4   = (const float*)d_in[11];
    const float* b_h4   = (const float*)d_in[12];
    float* out = (float*)d_out;

    cudaFuncSetAttribute(flatnet_mma_kernel,
                         cudaFuncAttributeMaxDynamicSharedMemorySize, SMEM_BYTES);
    // 148 CTAs x 8 warps; warp handles 16-row tiles t, t+1184 (2048 tiles total)
    flatnet_mma_kernel<<<148, THREADS, SMEM_BYTES>>>(
        pgi, W_lift, b_lift, W_code, b_code,
        W_h1, b_h1, W_h2, b_h2, W_h3, b_h3, W_h4, b_h4, out);
}